// round 8
// baseline (speedup 1.0000x reference)
#include <cuda_runtime.h>
#include <cuda_fp16.h>
#include <math.h>
#include <stdint.h>

#define BB 4
#define SS 2048
#define DDIM 1024
#define HH 16
#define DH 64

// Scratch (half): q,k,v projections, attention output, transposed weights
__device__ half g_qh[BB * SS * DDIM];
__device__ half g_kh[BB * SS * DDIM];
__device__ half g_vh[BB * SS * DDIM];
__device__ half g_xh[BB * SS * DDIM];
__device__ half g_wth[4][DDIM * DDIM];   // [n][k] = W[k][n]

// ---------------------------------------------------------------------------
// helpers
// ---------------------------------------------------------------------------
__device__ __forceinline__ uint32_t smem_u32(const void* p) {
    uint32_t a;
    asm("{ .reg .u64 t; cvta.to.shared.u64 t, %1; cvt.u32.u64 %0, t; }"
        : "=r"(a) : "l"(p));
    return a;
}

__device__ __forceinline__ uint32_t h2u(float x, float y) {
    half2 h = __floats2half2_rn(x, y);
    return *(uint32_t*)&h;
}

__device__ __forceinline__ void mma_f16(float* c, const uint32_t* a, const uint32_t* b) {
    asm volatile(
        "mma.sync.aligned.m16n8k16.row.col.f32.f16.f16.f32 "
        "{%0,%1,%2,%3}, {%4,%5,%6,%7}, {%8,%9}, {%0,%1,%2,%3};"
        : "+f"(c[0]), "+f"(c[1]), "+f"(c[2]), "+f"(c[3])
        : "r"(a[0]), "r"(a[1]), "r"(a[2]), "r"(a[3]),
          "r"(b[0]), "r"(b[1]));
}

__device__ __forceinline__ void ldsm_x4(uint32_t* r, uint32_t addr) {
    asm volatile("ldmatrix.sync.aligned.m8n8.x4.shared.b16 {%0,%1,%2,%3}, [%4];"
                 : "=r"(r[0]), "=r"(r[1]), "=r"(r[2]), "=r"(r[3]) : "r"(addr));
}
__device__ __forceinline__ void ldsm_x4_t(uint32_t* r, uint32_t addr) {
    asm volatile("ldmatrix.sync.aligned.m8n8.x4.trans.shared.b16 {%0,%1,%2,%3}, [%4];"
                 : "=r"(r[0]), "=r"(r[1]), "=r"(r[2]), "=r"(r[3]) : "r"(addr));
}

// ---------------------------------------------------------------------------
// Weight transpose: Wt[n][k] (half) = W[k][n] (float)
// ---------------------------------------------------------------------------
__global__ __launch_bounds__(256) void transpose_h(
    const float* __restrict__ src, half* __restrict__ dst)
{
    __shared__ float t[32][33];
    const int bx = blockIdx.x * 32;
    const int by = blockIdx.y * 32;
    const int tx = threadIdx.x;
    const int ty = threadIdx.y;
    for (int i = ty; i < 32; i += 8)
        t[i][tx] = src[(size_t)(by + i) * DDIM + bx + tx];
    __syncthreads();
    for (int i = ty; i < 32; i += 8)
        dst[(size_t)(bx + i) * DDIM + by + tx] = __float2half_rn(t[tx][i]);
}

// ---------------------------------------------------------------------------
// fp16 GEMM: C[M,1024] = A[M,1024] @ Wt[n][k]^T + bias
// BM=128, BN=128, BK=32, 256 threads (8 warps 4x2), warp tile 32x64.
// m16n8k16 mma, fragments via ldmatrix, stride 40 halves (BK=32 rows).
// ---------------------------------------------------------------------------
#define GST 40

template<bool AHALF, bool CHALF>
__global__ __launch_bounds__(256) void gemm_h(
    const void* __restrict__ Ain, const half* __restrict__ Bt,
    const float* __restrict__ bias, void* __restrict__ Cout)
{
    __shared__ half As[2][128 * GST];
    __shared__ half Bs[2][128 * GST];

    const int tid  = threadIdx.x;
    const int lane = tid & 31;
    const int warp = tid >> 5;
    const int wm   = (warp >> 1) * 32;
    const int wn   = (warp & 1) * 64;
    const int bm   = blockIdx.y * 128;
    const int bn   = blockIdx.x * 128;
    const int lr   = lane >> 2;
    const int lc   = lane & 3;

    float acc[2][8][4];
#pragma unroll
    for (int mi = 0; mi < 2; mi++)
#pragma unroll
        for (int nj = 0; nj < 8; nj++)
#pragma unroll
            for (int e = 0; e < 4; e++) acc[mi][nj][e] = 0.f;

    auto loadA = [&](int kt, int buf) {
        if (AHALF) {
            const half* A = (const half*)Ain;
#pragma unroll
            for (int p = 0; p < 2; p++) {
                int id = tid + p * 256;
                int r  = id >> 2;
                int cq = (id & 3) * 8;
                *(uint4*)&As[buf][r * GST + cq] =
                    *(const uint4*)&A[(size_t)(bm + r) * DDIM + kt * 32 + cq];
            }
        } else {
            const float* A = (const float*)Ain;
#pragma unroll
            for (int p = 0; p < 4; p++) {
                int id = tid + p * 256;
                int r  = id >> 3;
                int cq = (id & 7) * 4;
                float4 v = *(const float4*)&A[(size_t)(bm + r) * DDIM + kt * 32 + cq];
                *(half2*)&As[buf][r * GST + cq]     = __floats2half2_rn(v.x, v.y);
                *(half2*)&As[buf][r * GST + cq + 2] = __floats2half2_rn(v.z, v.w);
            }
        }
    };
    auto loadB = [&](int kt, int buf) {
#pragma unroll
        for (int p = 0; p < 2; p++) {
            int id = tid + p * 256;
            int r  = id >> 2;
            int cq = (id & 3) * 8;
            *(uint4*)&Bs[buf][r * GST + cq] =
                *(const uint4*)&Bt[(size_t)(bn + r) * DDIM + kt * 32 + cq];
        }
    };

    loadA(0, 0);
    loadB(0, 0);
    __syncthreads();

    for (int kt = 0; kt < 32; kt++) {
        const int buf = kt & 1;
        if (kt + 1 < 32) {
            loadA(kt + 1, buf ^ 1);
            loadB(kt + 1, buf ^ 1);
        }
        const uint32_t asb = smem_u32(&As[buf][0]);
        const uint32_t bsb = smem_u32(&Bs[buf][0]);
#pragma unroll
        for (int kk = 0; kk < 32; kk += 16) {
            uint32_t af[2][4];
#pragma unroll
            for (int mi = 0; mi < 2; mi++) {
                uint32_t addr = asb +
                    ((wm + mi * 16 + (lane & 15)) * GST + kk + (lane >> 4) * 8) * 2;
                ldsm_x4(af[mi], addr);
            }
            uint32_t bf[4][4];
#pragma unroll
            for (int p = 0; p < 4; p++) {
                uint32_t addr = bsb +
                    ((wn + p * 16 + (lane >> 4) * 8 + (lane & 7)) * GST +
                     kk + ((lane >> 3) & 1) * 8) * 2;
                ldsm_x4(bf[p], addr);
            }
#pragma unroll
            for (int p = 0; p < 4; p++)
#pragma unroll
                for (int mi = 0; mi < 2; mi++) {
                    mma_f16(acc[mi][2 * p],     af[mi], &bf[p][0]);
                    mma_f16(acc[mi][2 * p + 1], af[mi], &bf[p][2]);
                }
        }
        __syncthreads();
    }

    // epilogue
#pragma unroll
    for (int mi = 0; mi < 2; mi++) {
#pragma unroll
        for (int nj = 0; nj < 8; nj++) {
            int row = bm + wm + mi * 16 + lr;
            int col = bn + wn + nj * 8 + 2 * lc;
            float b0 = bias[col], b1 = bias[col + 1];
            float v0 = acc[mi][nj][0] + b0;
            float v1 = acc[mi][nj][1] + b1;
            float v2 = acc[mi][nj][2] + b0;
            float v3 = acc[mi][nj][3] + b1;
            if (CHALF) {
                half* C = (half*)Cout;
                *(half2*)&C[(size_t)row * DDIM + col]       = __floats2half2_rn(v0, v1);
                *(half2*)&C[(size_t)(row + 8) * DDIM + col] = __floats2half2_rn(v2, v3);
            } else {
                float* C = (float*)Cout;
                *(float2*)&C[(size_t)row * DDIM + col]       = make_float2(v0, v1);
                *(float2*)&C[(size_t)(row + 8) * DDIM + col] = make_float2(v2, v3);
            }
        }
    }
}

// ---------------------------------------------------------------------------
// Causal flash attention, fp16 mma, fp32 softmax/accum.
// grid = (S/128, B*H); block 256 (8 warps); Q tile 128, KV tiles 64.
// Each warp owns 16 query rows; P stays in registers (S c-frag == PV a-frag).
// Smem row stride 72 halves (rows are 64 halves wide): 144B rows, ldmatrix
// conflict-free (r*144 mod 128 = r*16 covers all banks).
// ---------------------------------------------------------------------------
#define AST 72

__global__ __launch_bounds__(256) void attn_h()
{
    __shared__ half Qs[128 * AST];
    __shared__ half Ks[64 * AST];
    __shared__ half Vs[64 * AST];

    const int tid  = threadIdx.x;
    const int lane = tid & 31;
    const int warp = tid >> 5;          // 0..7
    const int lr   = lane >> 2;
    const int lc   = lane & 3;
    const int qt   = blockIdx.x;        // 0..15
    const int bh   = blockIdx.y;
    const int b    = bh >> 4;
    const int h    = bh & 15;
    const int q0   = qt * 128;
    const int rw   = warp * 16;
    const float scale = 0.125f;

    const size_t base = (size_t)b * SS * DDIM + (size_t)h * DH;

    // Load Q tile 128x64 halves
#pragma unroll
    for (int p = 0; p < 4; p++) {
        int id = tid + p * 256;          // 0..1023
        int r  = id >> 3;                // 0..127
        int cq = (id & 7) * 8;
        *(uint4*)&Qs[r * AST + cq] =
            *(const uint4*)&g_qh[base + (size_t)(q0 + r) * DDIM + cq];
    }

    float o[8][4];
#pragma unroll
    for (int nj = 0; nj < 8; nj++)
#pragma unroll
        for (int e = 0; e < 4; e++) o[nj][e] = 0.f;
    float m0 = -INFINITY, m1 = -INFINITY, l0 = 0.f, l1 = 0.f;

    const uint32_t qsb = smem_u32(Qs);
    const uint32_t ksb = smem_u32(Ks);
    const uint32_t vsb = smem_u32(Vs);

    const int kvt_max = 2 * qt + 1;
    for (int kvt = 0; kvt <= kvt_max; kvt++) {
        const int kv0 = kvt * 64;
        // Load K, V tiles (64x64 halves each)
#pragma unroll
        for (int p = 0; p < 2; p++) {
            int id = tid + p * 256;      // 0..511
            int r  = id >> 3;            // 0..63
            int cq = (id & 7) * 8;
            size_t goff = base + (size_t)(kv0 + r) * DDIM + cq;
            *(uint4*)&Ks[r * AST + cq] = *(const uint4*)&g_kh[goff];
            *(uint4*)&Vs[r * AST + cq] = *(const uint4*)&g_vh[goff];
        }
        __syncthreads();

        // S = Q @ K^T  (warp tile 16x64)
        float sfr[8][4];
#pragma unroll
        for (int nj = 0; nj < 8; nj++)
#pragma unroll
            for (int e = 0; e < 4; e++) sfr[nj][e] = 0.f;

#pragma unroll
        for (int kk = 0; kk < 64; kk += 16) {
            uint32_t af[4];
            ldsm_x4(af, qsb + ((rw + (lane & 15)) * AST + kk + (lane >> 4) * 8) * 2);
#pragma unroll
            for (int p = 0; p < 4; p++) {
                uint32_t bf[4];
                ldsm_x4(bf, ksb + ((p * 16 + (lane >> 4) * 8 + (lane & 7)) * AST +
                                   kk + ((lane >> 3) & 1) * 8) * 2);
                mma_f16(sfr[2 * p],     af, &bf[0]);
                mma_f16(sfr[2 * p + 1], af, &bf[2]);
            }
        }

        // scale + causal mask
        const int row0g = q0 + rw + lr;
        const int row1g = row0g + 8;
        const bool need_mask = (kv0 + 63 > row0g);
#pragma unroll
        for (int nj = 0; nj < 8; nj++) {
#pragma unroll
            for (int e = 0; e < 4; e++) sfr[nj][e] *= scale;
            if (need_mask) {
                int c0 = kv0 + nj * 8 + 2 * lc;
                if (c0 > row0g)     sfr[nj][0] = -INFINITY;
                if (c0 + 1 > row0g) sfr[nj][1] = -INFINITY;
                if (c0 > row1g)     sfr[nj][2] = -INFINITY;
                if (c0 + 1 > row1g) sfr[nj][3] = -INFINITY;
            }
        }

        // online softmax (rows row0g, row1g spread over 4 lanes)
        float mt0 = -INFINITY, mt1 = -INFINITY;
#pragma unroll
        for (int nj = 0; nj < 8; nj++) {
            mt0 = fmaxf(mt0, fmaxf(sfr[nj][0], sfr[nj][1]));
            mt1 = fmaxf(mt1, fmaxf(sfr[nj][2], sfr[nj][3]));
        }
        mt0 = fmaxf(mt0, __shfl_xor_sync(0xffffffffu, mt0, 1, 4));
        mt0 = fmaxf(mt0, __shfl_xor_sync(0xffffffffu, mt0, 2, 4));
        mt1 = fmaxf(mt1, __shfl_xor_sync(0xffffffffu, mt1, 1, 4));
        mt1 = fmaxf(mt1, __shfl_xor_sync(0xffffffffu, mt1, 2, 4));

        float mn0 = fmaxf(m0, mt0);
        float mn1 = fmaxf(m1, mt1);
        float a0 = __expf(m0 - mn0);
        float a1 = __expf(m1 - mn1);
        m0 = mn0; m1 = mn1;

        float rs0 = 0.f, rs1 = 0.f;
#pragma unroll
        for (int nj = 0; nj < 8; nj++) {
            sfr[nj][0] = __expf(sfr[nj][0] - mn0);
            sfr[nj][1] = __expf(sfr[nj][1] - mn0);
            sfr[nj][2] = __expf(sfr[nj][2] - mn1);
            sfr[nj][3] = __expf(sfr[nj][3] - mn1);
            rs0 += sfr[nj][0] + sfr[nj][1];
            rs1 += sfr[nj][2] + sfr[nj][3];
        }
        rs0 += __shfl_xor_sync(0xffffffffu, rs0, 1, 4);
        rs0 += __shfl_xor_sync(0xffffffffu, rs0, 2, 4);
        rs1 += __shfl_xor_sync(0xffffffffu, rs1, 1, 4);
        rs1 += __shfl_xor_sync(0xffffffffu, rs1, 2, 4);
        l0 = l0 * a0 + rs0;
        l1 = l1 * a1 + rs1;
#pragma unroll
        for (int nj = 0; nj < 8; nj++) {
            o[nj][0] *= a0; o[nj][1] *= a0;
            o[nj][2] *= a1; o[nj][3] *= a1;
        }

        // O += P @ V : P a-frags built directly from sfr (c-frag == a-frag)
#pragma unroll
        for (int kki = 0; kki < 4; kki++) {
            uint32_t pa[4];
            pa[0] = h2u(sfr[2 * kki][0],     sfr[2 * kki][1]);
            pa[1] = h2u(sfr[2 * kki][2],     sfr[2 * kki][3]);
            pa[2] = h2u(sfr[2 * kki + 1][0], sfr[2 * kki + 1][1]);
            pa[3] = h2u(sfr[2 * kki + 1][2], sfr[2 * kki + 1][3]);
#pragma unroll
            for (int p = 0; p < 4; p++) {
                uint32_t vf[4];
                ldsm_x4_t(vf, vsb + ((kki * 16 + (lane & 15)) * AST +
                                     p * 16 + (lane >> 4) * 8) * 2);
                mma_f16(o[2 * p],     pa, &vf[0]);
                mma_f16(o[2 * p + 1], pa, &vf[2]);
            }
        }
        __syncthreads();   // protect Ks/Vs before next load
    }

    // normalize, write half output
    float inv0 = 1.f / l0;
    float inv1 = 1.f / l1;
    const int row0g = q0 + rw + lr;
    size_t r0off = base + (size_t)row0g * DDIM;
    size_t r1off = base + (size_t)(row0g + 8) * DDIM;
#pragma unroll
    for (int nj = 0; nj < 8; nj++) {
        int cl = nj * 8 + 2 * lc;
        *(half2*)&g_xh[r0off + cl] = __floats2half2_rn(o[nj][0] * inv0, o[nj][1] * inv0);
        *(half2*)&g_xh[r1off + cl] = __floats2half2_rn(o[nj][2] * inv1, o[nj][3] * inv1);
    }
}

// ---------------------------------------------------------------------------
// Launch
// ---------------------------------------------------------------------------
extern "C" void kernel_launch(void* const* d_in, const int* in_sizes, int n_in,
                              void* d_out, int out_size)
{
    (void)in_sizes; (void)n_in; (void)out_size;

    const float* query = (const float*)d_in[0];
    const float* key   = (const float*)d_in[1];
    const float* value = (const float*)d_in[2];
    // d_in[3] = mask — applied analytically
    const float* Wq = (const float*)d_in[4];
    const float* bq = (const float*)d_in[5];
    const float* Wk = (const float*)d_in[6];
    const float* bk = (const float*)d_in[7];
    const float* Wv = (const float*)d_in[8];
    const float* bv = (const float*)d_in[9];
    const float* Wo = (const float*)d_in[10];
    const float* bo = (const float*)d_in[11];
    float* out = (float*)d_out;

    half *pq, *pk, *pv, *px, *pwt;
    cudaGetSymbolAddress((void**)&pq, g_qh);
    cudaGetSymbolAddress((void**)&pk, g_kh);
    cudaGetSymbolAddress((void**)&pv, g_vh);
    cudaGetSymbolAddress((void**)&px, g_xh);
    cudaGetSymbolAddress((void**)&pwt, g_wth);
    half* wtq = pwt;
    half* wtk = pwt + (size_t)DDIM * DDIM;
    half* wtv = pwt + 2 * (size_t)DDIM * DDIM;
    half* wto = pwt + 3 * (size_t)DDIM * DDIM;

    // transpose + halve weights
    dim3 tgrid(DDIM / 32, DDIM / 32);
    dim3 tblock(32, 8);
    transpose_h<<<tgrid, tblock>>>(Wq, wtq);
    transpose_h<<<tgrid, tblock>>>(Wk, wtk);
    transpose_h<<<tgrid, tblock>>>(Wv, wtv);
    transpose_h<<<tgrid, tblock>>>(Wo, wto);

    const int M = BB * SS;   // 8192
    dim3 ggrid(DDIM / 128, M / 128);   // (8, 64)

    gemm_h<false, true><<<ggrid, 256>>>(query, wtq, bq, pq);
    gemm_h<false, true><<<ggrid, 256>>>(key,   wtk, bk, pk);
    gemm_h<false, true><<<ggrid, 256>>>(value, wtv, bv, pv);

    dim3 attn_grid(SS / 128, BB * HH);   // (16, 64)
    attn_h<<<attn_grid, 256>>>();

    gemm_h<true, false><<<ggrid, 256>>>(px, wto, bo, out);
}